// round 5
// baseline (speedup 1.0000x reference)
#include <cuda_runtime.h>
#include <cuda_bf16.h>

#define T_ 128
#define B_ 512
#define D_ 500
#define D4_ 125   // D/4 float4 per row

// Scratch (no allocation allowed): control-plane metadata.
// g_meta[b*T_+t]: bit0 = token t valid; bits[1:15] = (seg_to_emit_after_t + 1), 0 = none.
__device__ unsigned short g_meta[B_ * T_];
__device__ int g_newlen[B_];
__device__ int g_order[B_];

// ---------------------------------------------------------------------------
// Kernel 1: per-column greedy packing scan (control plane).
// One block (128 threads) per batch column. Threads gather token lengths in
// parallel; lane 0 bulk-loads them into registers and runs a branchless
// 128-step greedy scan, attaching "emit segment s after row t" flags to the
// LAST valid token of each segment (so the merge kernel can stream rows in
// t-order and flush its accumulator exactly at segment ends).
// ---------------------------------------------------------------------------
__global__ __launch_bounds__(T_) void setup_kernel(const int* __restrict__ src,
                                                   const int* __restrict__ token_lengths,
                                                   const int* __restrict__ token_len_p)
{
    __shared__ uint4 s_len4[T_ / 16];          // 128 bytes of lengths
    __shared__ unsigned short s_meta[T_];

    int b = blockIdx.x;
    int t = threadIdx.x;

    // Parallel gather phase.
    int s = src[t * B_ + b];
    int l = (s == 1) ? 0 : ((s == 0) ? 4 : token_lengths[s]);
    ((unsigned char*)s_len4)[t] = (unsigned char)l;
    s_meta[t] = 0;
    __syncthreads();

    if (t == 0) {
        int token_len = token_len_p ? token_len_p[0] : 20;

        // Bulk-load all 128 length bytes into registers (8x LDS.128).
        uint w[T_ / 4];
        #pragma unroll
        for (int i = 0; i < T_ / 16; i++) {
            uint4 v = s_len4[i];
            w[i * 4 + 0] = v.x; w[i * 4 + 1] = v.y;
            w[i * 4 + 2] = v.z; w[i * 4 + 3] = v.w;
        }

        int seg = 0, curr = 0, last_t = 0;
        #pragma unroll
        for (int tt = 0; tt < T_; tt++) {
            int ll = (w[tt >> 2] >> ((tt & 3) * 8)) & 0xFF;
            bool valid = (ll != 0);
            bool close = valid & (curr > 0) & (curr + ll > token_len);
            if (close) s_meta[last_t] |= (unsigned short)((seg + 1) << 1);
            seg  += (int)close;
            curr  = close ? 0 : curr;
            if (valid) s_meta[tt] |= 1;
            curr  += valid ? ll : 0;
            last_t = valid ? tt : last_t;
        }
        bool trail = (curr > 0);                 // open trailing segment
        if (trail) s_meta[last_t] |= (unsigned short)((seg + 1) << 1);
        seg += (int)trail;
        g_newlen[b] = seg;
    }
    __syncthreads();

    // Cooperative writeback of metadata.
    g_meta[b * T_ + t] = s_meta[t];
}

// ---------------------------------------------------------------------------
// Kernel 2: stable descending rank (== jnp.argsort(-new_lengths), stable).
// Grid-parallel: one 128-thread block per column b. Each thread handles 4
// entries (int4 load), block-reduces the predicate count, thread 0 scatters.
// ---------------------------------------------------------------------------
__global__ __launch_bounds__(128) void order_kernel(float* __restrict__ out_len,
                                                    int write_len)
{
    __shared__ int s_warp[4];
    int b = blockIdx.x;
    int t = threadIdx.x;
    int myl = g_newlen[b];

    const int4* len4 = (const int4*)g_newlen;
    int4 v = len4[t];                  // j = 4t .. 4t+3
    int j = 4 * t;
    int cnt = 0;
    cnt += (v.x > myl) || (v.x == myl && (j + 0) < b);
    cnt += (v.y > myl) || (v.y == myl && (j + 1) < b);
    cnt += (v.z > myl) || (v.z == myl && (j + 2) < b);
    cnt += (v.w > myl) || (v.w == myl && (j + 3) < b);

    #pragma unroll
    for (int o = 16; o > 0; o >>= 1) cnt += __shfl_down_sync(0xFFFFFFFFu, cnt, o);
    if ((t & 31) == 0) s_warp[t >> 5] = cnt;
    __syncthreads();
    if (t == 0) {
        int rank = s_warp[0] + s_warp[1] + s_warp[2] + s_warp[3];
        g_order[rank] = b;
        if (write_len) out_len[rank] = (float)myl;
    }
}

// ---------------------------------------------------------------------------
// Kernel 3: fused streaming data plane — reads each input row ONCE.
// One block per output column bo (source b = order[bo]); thread i owns
// float4 chunk i of the row. Stream t = 0..127:
//   - valid row  -> add into running accumulator (segments contiguous in t)
//   - t >= L     -> write row through to out[t, bo]  (original values kept)
//   - emit flag  -> flush accumulator into out[seg, bo], reset
// Traffic: 128 reads + 128 writes per column = 262 MB total (was 363 MB).
// ---------------------------------------------------------------------------
__global__ __launch_bounds__(T_) void merge_kernel(const float4* __restrict__ embv,
                                                   float4* __restrict__ outv)
{
    __shared__ unsigned short s_meta[T_];

    int bo = blockIdx.x;
    int i  = threadIdx.x;
    int b  = g_order[bo];
    int L  = g_newlen[b];

    s_meta[i] = g_meta[b * T_ + i];
    __syncthreads();

    bool active = (i < D4_);
    float4 acc = make_float4(0.f, 0.f, 0.f, 0.f);

    #pragma unroll 4
    for (int t = 0; t < T_; t++) {
        float4 v = make_float4(0.f, 0.f, 0.f, 0.f);
        if (active) v = embv[(long)(t * B_ + b) * D4_ + i];
        unsigned int m = s_meta[t];

        if (m & 1u) {
            acc.x += v.x; acc.y += v.y; acc.z += v.z; acc.w += v.w;
        }
        if (t >= L && active)
            outv[(long)(t * B_ + bo) * D4_ + i] = v;

        unsigned int e = m >> 1;
        if (e && active) {
            outv[(long)(((int)e - 1) * B_ + bo) * D4_ + i] = acc;
            acc = make_float4(0.f, 0.f, 0.f, 0.f);
        }
    }
}

// ---------------------------------------------------------------------------
extern "C" void kernel_launch(void* const* d_in, const int* in_sizes, int n_in,
                              void* d_out, int out_size)
{
    const float* emb           = (const float*)d_in[0];   // (T,B,D) fp32
    const int*   src           = (const int*)d_in[1];     // (T,B) int32
    // d_in[2] = lengths (unused by reference computation)
    const int*   token_lengths = (const int*)d_in[3];     // (VOCAB,) int32
    const int*   token_len_p   = (n_in >= 5) ? (const int*)d_in[4] : nullptr;

    float* out = (float*)d_out;
    const long emb_elems = (long)T_ * B_ * D_;
    int write_len = (out_size >= emb_elems + B_) ? 1 : 0;

    setup_kernel<<<B_, T_>>>(src, token_lengths, token_len_p);
    order_kernel<<<B_, 128>>>(out + emb_elems, write_len);
    merge_kernel<<<B_, T_>>>((const float4*)emb, (float4*)out);
}

// round 6
// speedup vs baseline: 1.3748x; 1.3748x over previous
#include <cuda_runtime.h>
#include <cuda_bf16.h>

#define T_ 128
#define B_ 512
#define D_ 500
#define D4_ 125   // D/4 float4 per row
#define PF 8      // prefetch depth (rows ahead)

// Scratch (no allocation allowed): control-plane metadata.
// g_meta[b*T_+t]: bit0 = token t valid; bits[1:15] = (seg_to_emit_after_t + 1), 0 = none.
__device__ unsigned short g_meta[B_ * T_];
__device__ int g_newlen[B_];

// ---------------------------------------------------------------------------
// Kernel 1: per-column greedy packing scan (control plane).
// One block (128 threads) per batch column. Threads gather token lengths in
// parallel; lane 0 bulk-loads them into registers and runs a branchless
// 128-step greedy scan, attaching "emit segment s after row t" flags to the
// LAST valid token of each segment.
// ---------------------------------------------------------------------------
__global__ __launch_bounds__(T_) void setup_kernel(const int* __restrict__ src,
                                                   const int* __restrict__ token_lengths,
                                                   const int* __restrict__ token_len_p)
{
    __shared__ uint4 s_len4[T_ / 16];          // 128 bytes of lengths
    __shared__ unsigned short s_meta[T_];

    int b = blockIdx.x;
    int t = threadIdx.x;

    // Parallel gather phase.
    int s = src[t * B_ + b];
    int l = (s == 1) ? 0 : ((s == 0) ? 4 : token_lengths[s]);
    ((unsigned char*)s_len4)[t] = (unsigned char)l;
    s_meta[t] = 0;
    __syncthreads();

    if (t == 0) {
        int token_len = token_len_p ? token_len_p[0] : 20;

        // Bulk-load all 128 length bytes into registers (8x LDS.128).
        uint w[T_ / 4];
        #pragma unroll
        for (int i = 0; i < T_ / 16; i++) {
            uint4 v = s_len4[i];
            w[i * 4 + 0] = v.x; w[i * 4 + 1] = v.y;
            w[i * 4 + 2] = v.z; w[i * 4 + 3] = v.w;
        }

        int seg = 0, curr = 0, last_t = 0;
        #pragma unroll
        for (int tt = 0; tt < T_; tt++) {
            int ll = (w[tt >> 2] >> ((tt & 3) * 8)) & 0xFF;
            bool valid = (ll != 0);
            bool close = valid & (curr > 0) & (curr + ll > token_len);
            if (close) s_meta[last_t] |= (unsigned short)((seg + 1) << 1);
            seg  += (int)close;
            curr  = close ? 0 : curr;
            if (valid) s_meta[tt] |= 1;
            curr  += valid ? ll : 0;
            last_t = valid ? tt : last_t;
        }
        bool trail = (curr > 0);                 // open trailing segment
        if (trail) s_meta[last_t] |= (unsigned short)((seg + 1) << 1);
        seg += (int)trail;
        g_newlen[b] = seg;
    }
    __syncthreads();

    // Cooperative writeback of metadata.
    g_meta[b * T_ + t] = s_meta[t];
}

// ---------------------------------------------------------------------------
// Kernel 2 (fused data plane + rank): one block per SOURCE column b.
//   - Immediately issues PF=8 prefetch loads of the first embedding rows
//     (latency hidden under everything below).
//   - Computes this column's stable descending rank bo over g_newlen
//     (replaces the old order_kernel entirely).
//   - Streams t = 0..127 with an 8-deep load pipeline, reading each input
//     row exactly once: accumulate valid rows, write-through rows t >= L,
//     flush the accumulator into out[seg] at segment-end flags.
// Traffic: 128 reads + 128 writes per column = 262 MB total.
// ---------------------------------------------------------------------------
__global__ __launch_bounds__(T_) void merge_kernel(const float4* __restrict__ embv,
                                                   float4* __restrict__ outv,
                                                   float* __restrict__ out_len,
                                                   int write_len)
{
    __shared__ unsigned short s_meta[T_];
    __shared__ int s_warp[4];
    __shared__ int s_rank;

    int b = blockIdx.x;
    int i = threadIdx.x;

    const long stride = (long)B_ * D4_;        // float4s per t-slab
    bool active = (i < D4_);
    int  ic     = active ? i : (D4_ - 1);      // clamped: loads always valid
    long ibase  = (long)b * D4_ + ic;

    // ---- kick off prefetch pipeline first (deep MLP) ----
    float4 buf[PF];
    #pragma unroll
    for (int k = 0; k < PF; k++) buf[k] = embv[ibase + (long)k * stride];

    // ---- overlap: meta load + rank reduction while loads are in flight ----
    s_meta[i] = g_meta[b * T_ + i];

    int myl = g_newlen[b];
    const int4* len4 = (const int4*)g_newlen;  // 512 / 4 = 128 == blockDim
    int4 v4 = len4[i];
    int j = 4 * i;
    int cnt = 0;
    cnt += (v4.x > myl) || (v4.x == myl && (j + 0) < b);
    cnt += (v4.y > myl) || (v4.y == myl && (j + 1) < b);
    cnt += (v4.z > myl) || (v4.z == myl && (j + 2) < b);
    cnt += (v4.w > myl) || (v4.w == myl && (j + 3) < b);
    #pragma unroll
    for (int o = 16; o > 0; o >>= 1) cnt += __shfl_down_sync(0xFFFFFFFFu, cnt, o);
    if ((i & 31) == 0) s_warp[i >> 5] = cnt;
    __syncthreads();
    if (i == 0) {
        int rank = s_warp[0] + s_warp[1] + s_warp[2] + s_warp[3];
        s_rank = rank;
        if (write_len) out_len[rank] = (float)myl;
    }
    __syncthreads();

    int  bo    = s_rank;
    int  L     = myl;
    long obase = (long)bo * D4_ + i;

    // ---- streaming loop with 8-deep ring buffer ----
    float4 acc = make_float4(0.f, 0.f, 0.f, 0.f);

    for (int to = 0; to < T_; to += PF) {
        #pragma unroll
        for (int k = 0; k < PF; k++) {
            int t = to + k;
            float4 v = buf[k];
            if (t + PF < T_)                       // refill slot (stays 8 ahead)
                buf[k] = embv[ibase + (long)(t + PF) * stride];

            unsigned int m = s_meta[t];
            if (m & 1u) {
                acc.x += v.x; acc.y += v.y; acc.z += v.z; acc.w += v.w;
            }
            if (t >= L && active)
                outv[obase + (long)t * stride] = v;

            unsigned int e = m >> 1;
            if (e && active) {
                outv[obase + (long)((int)e - 1) * stride] = acc;
                acc = make_float4(0.f, 0.f, 0.f, 0.f);
            }
        }
    }
}

// ---------------------------------------------------------------------------
extern "C" void kernel_launch(void* const* d_in, const int* in_sizes, int n_in,
                              void* d_out, int out_size)
{
    const float* emb           = (const float*)d_in[0];   // (T,B,D) fp32
    const int*   src           = (const int*)d_in[1];     // (T,B) int32
    // d_in[2] = lengths (unused by reference computation)
    const int*   token_lengths = (const int*)d_in[3];     // (VOCAB,) int32
    const int*   token_len_p   = (n_in >= 5) ? (const int*)d_in[4] : nullptr;

    float* out = (float*)d_out;
    const long emb_elems = (long)T_ * B_ * D_;
    int write_len = (out_size >= emb_elems + B_) ? 1 : 0;

    setup_kernel<<<B_, T_>>>(src, token_lengths, token_len_p);
    merge_kernel<<<B_, T_>>>((const float4*)emb, (float4*)out,
                             out + emb_elems, write_len);
}